// round 5
// baseline (speedup 1.0000x reference)
#include <cuda_runtime.h>
#include <math.h>

#define K_TOP 512
#define CAP 4096

// level dims
#define D1 48
#define H1 96
#define W1 96
#define NV1 (D1*H1*W1)   // 442368
#define D2 24
#define H2 48
#define W2 48
#define NV2 (D2*H2*W2)   // 55296
#define D3 12
#define H3 24
#define W3 24
#define NV3 (D3*H3*W3)   // 6912

// ------------------------------------------------------------------
// Kahan-compensated accumulation with exact product (TwoProd+TwoSum).
// Gives effectively correctly-rounded sums independent of term order,
// removing our half of the mine-vs-reference rounding-noise delta.
// ------------------------------------------------------------------
__device__ __forceinline__ void kacc(float& s, float& c, float a, float b){
  float p = __fmul_rn(a,b);
  float e = __fmaf_rn(a,b,-p);                 // exact product low part
  float t = __fadd_rn(s,p);
  float z = __fsub_rn(t,s);
  float err = __fadd_rn(__fsub_rn(s,__fsub_rn(t,z)), __fsub_rn(p,z));
  s = t;
  c = __fadd_rn(c, __fadd_rn(err,e));
}
__device__ __forceinline__ float kfin(float s, float c){
  return (float)((double)s + (double)c);       // near-correctly-rounded total
}

// ------------------------------------------------------------------
// scratch (static __device__, no runtime allocation)
// ------------------------------------------------------------------
__device__ float g_f1[16*NV1];
__device__ float g_f2[32*NV2];
__device__ float g_f3[64*NV3];
__device__ float g_p1[32*NV1];
__device__ float g_p2[32*NV2];
__device__ float g_p3[32*NV3];
__device__ float g_s1[NV1];
__device__ float g_s2[NV2];
__device__ float g_s3[NV3];
__device__ float g_c1t[432];      // [k27][o16]
__device__ float g_c2t[13824];    // [k27][ci16][o32]
__device__ float g_c3t[55296];    // [k27][ci32][o64]
__device__ float g_l1t[512];      // [ci16][c32]
__device__ float g_l2t[1024];     // [ci32][c32]
__device__ float g_l3t[2048];     // [ci64][c32]
__device__ unsigned g_hist16[65536];
__device__ unsigned g_hist8[256];
__device__ int g_ctrl[8];         // [0]=b16 [1]=cntAbove16 [2]=thresh24 [3]=candCount
__device__ unsigned g_candKey[CAP];
__device__ unsigned g_candIdx[CAP];
__device__ float g_topval[3*K_TOP];
__device__ unsigned g_topidx[3*K_TOP];

// ------------------------------------------------------------------
// weight transposition (once per launch; cheap)
// ------------------------------------------------------------------
__global__ void prep_k(const float* __restrict__ c1w, const float* __restrict__ c2w,
                       const float* __restrict__ c3w, const float* __restrict__ l1w,
                       const float* __restrict__ l2w, const float* __restrict__ l3w){
  int t = blockIdx.x*blockDim.x + threadIdx.x;
  if (t < 432){ int k=t/16, o=t%16; g_c1t[t] = c1w[o*27+k]; }
  if (t < 13824){ int k=t/512; int ci=(t>>5)&15; int o=t&31; g_c2t[t]=c2w[(o*16+ci)*27+k]; }
  if (t < 55296){ int k=t/2048; int ci=(t>>6)&31; int o=t&63; g_c3t[t]=c3w[(o*32+ci)*27+k]; }
  if (t < 512){ int ci=t/32, c=t%32; g_l1t[t]=l1w[c*16+ci]; }
  if (t < 1024){ int ci=t/32, c=t%32; g_l2t[t]=l2w[c*32+ci]; }
  if (t < 2048){ int ci=t/32, c=t%32; g_l3t[t]=l3w[c*64+ci]; }
}

// ------------------------------------------------------------------
// conv1: [1,96,192,192] -> relu -> f1 [16,48,96,96], 3x3x3 s2 SAME
// ------------------------------------------------------------------
__global__ void conv1_k(const float* __restrict__ x, const float* __restrict__ b){
  __shared__ float4 ws[108];
  __shared__ float bs[16];
  int tid = threadIdx.x;
  if (tid < 108) ws[tid] = ((const float4*)g_c1t)[tid];
  if (tid < 16) bs[tid] = b[tid];
  __syncthreads();
  int v = blockIdx.x*256 + tid;
  int z = v / (H1*W1); int r = v % (H1*W1); int y = r / W1; int xx = r % W1;
  float aS[16], aC[16];
#pragma unroll
  for (int o=0;o<16;o++){ aS[o]=0.f; aC[o]=0.f; }
#pragma unroll
  for (int kd=0;kd<3;kd++){
    int iz=2*z+kd; bool okz = iz<96;
#pragma unroll
    for (int kh=0;kh<3;kh++){
      int iy=2*y+kh; bool oky = iy<192;
#pragma unroll
      for (int kw=0;kw<3;kw++){
        int ix=2*xx+kw;
        if (okz && oky && ix<192){
          float in = __ldg(&x[(iz*192+iy)*192+ix]);
          int k=(kd*3+kh)*3+kw;
#pragma unroll
          for (int j=0;j<4;j++){
            float4 w = ws[k*4+j];
            kacc(aS[j*4+0],aC[j*4+0],in,w.x); kacc(aS[j*4+1],aC[j*4+1],in,w.y);
            kacc(aS[j*4+2],aC[j*4+2],in,w.z); kacc(aS[j*4+3],aC[j*4+3],in,w.w);
          }
        }
      }
    }
  }
#pragma unroll
  for (int o=0;o<16;o++)
    g_f1[o*NV1+v] = fmaxf(__fadd_rn(kfin(aS[o],aC[o]),bs[o]),0.f);
}

// ------------------------------------------------------------------
// conv2: f1 [16,48,96,96] -> relu -> f2 [32,24,48,48]
// ------------------------------------------------------------------
__global__ void conv2_k(const float* __restrict__ b){
  __shared__ float4 ws[1152];   // 9 taps * 16ci * 8 float4 = 18KB
  int tid=threadIdx.x;
  int v = blockIdx.x*256+tid;
  int z=v/(H2*W2); int r=v%(H2*W2); int y=r/W2; int xx=r%W2;
  float aS[32], aC[32];
#pragma unroll
  for(int o=0;o<32;o++){ aS[o]=0.f; aC[o]=0.f; }
  for(int kd=0;kd<3;kd++){
    __syncthreads();
    for(int i=tid;i<4608;i+=256) ((float*)ws)[i]=g_c2t[kd*4608+i];
    __syncthreads();
    int iz=2*z+kd; bool okz=iz<D1;
#pragma unroll
    for(int kh=0;kh<3;kh++){
      int iy=2*y+kh; bool oky=iy<H1;
#pragma unroll
      for(int kw=0;kw<3;kw++){
        int ix=2*xx+kw;
        if(okz && oky && ix<W1){
          int off=(iz*H1+iy)*W1+ix;
          int kl=kh*3+kw;
#pragma unroll
          for(int ci=0;ci<16;ci++){
            float in=__ldg(&g_f1[ci*NV1+off]);
            const float4* wr=&ws[(kl*16+ci)*8];
#pragma unroll
            for(int j=0;j<8;j++){
              float4 w=wr[j];
              kacc(aS[j*4+0],aC[j*4+0],in,w.x); kacc(aS[j*4+1],aC[j*4+1],in,w.y);
              kacc(aS[j*4+2],aC[j*4+2],in,w.z); kacc(aS[j*4+3],aC[j*4+3],in,w.w);
            }
          }
        }
      }
    }
  }
#pragma unroll
  for(int o=0;o<32;o++)
    g_f2[o*NV2+v]=fmaxf(__fadd_rn(kfin(aS[o],aC[o]),__ldg(&b[o])),0.f);
}

// ------------------------------------------------------------------
// conv3: f2 [32,24,48,48] -> relu -> f3 [64,12,24,24]
// ------------------------------------------------------------------
__global__ void conv3_k(const float* __restrict__ b){
  __shared__ float4 ws[1024];   // 2 taps * 32ci * 16 float4 = 16KB
  __shared__ float shin[7200];  // 32ci * 5*5*9 = 28.8KB
  int tid=threadIdx.x;
  int bt=blockIdx.x;
  int btz=bt/72; int rem=bt%72; int bty=rem/6; int btx=rem%6;
  int og=tid&15; int vi=tid>>4;
  int vz=vi>>3; int vy=(vi>>2)&1; int vx=vi&3;
  int z0=btz*4, y0=bty*4, x0=btx*8;
  for(int i=tid;i<7200;i+=256){
    int cl=i/225; int r=i%225; int lz=r/45; int r2=r%45; int ly=r2/9; int lx=r2%9;
    int gz=z0+lz, gy=y0+ly, gx=x0+lx;
    shin[i]=(gz<D2&&gy<H2&&gx<W2)? g_f2[cl*NV2+(gz*H2+gy)*W2+gx] : 0.f;
  }
  float aS[4]={0.f,0.f,0.f,0.f}, aC[4]={0.f,0.f,0.f,0.f};
  int sbase=(2*vz)*45+(2*vy)*9+(2*vx);
  for(int ph=0; ph<14; ph++){
    int ktaps=(ph==13)?1:2;
    __syncthreads();
    for(int i=tid;i<ktaps*2048;i+=256) ((float*)ws)[i]=g_c3t[ph*4096+i];
    __syncthreads();
    for(int kl=0;kl<ktaps;kl++){
      int k=ph*2+kl;
      int kd=k/9, kh=(k%9)/3, kw=k%3;
      const float* sh=&shin[sbase + kd*45 + kh*9 + kw];
      const float4* wb=&ws[kl*512+og];
#pragma unroll
      for(int ci=0;ci<32;ci++){
        float in=sh[ci*225];
        float4 w=wb[ci*16];
        kacc(aS[0],aC[0],in,w.x); kacc(aS[1],aC[1],in,w.y);
        kacc(aS[2],aC[2],in,w.z); kacc(aS[3],aC[3],in,w.w);
      }
    }
  }
  int oz=btz*2+vz, oy=bty*2+vy, ox=btx*4+vx;
  int v=(oz*H3+oy)*W3+ox;
#pragma unroll
  for(int j=0;j<4;j++){
    int c=og*4+j;
    g_f3[c*NV3+v]=fmaxf(__fadd_rn(kfin(aS[j],aC[j]),__ldg(&b[c])),0.f);
  }
}

// ------------------------------------------------------------------
// FPN laterals + top-down adds + per-voxel channel-max score
// final rounding sequence matches ref: float(conv) +b (fp32) +up2 (fp32)
// ------------------------------------------------------------------
__global__ void p3_k(const float* __restrict__ b){
  __shared__ float4 lw[512];
  int tid=threadIdx.x;
  for(int i=tid;i<512;i+=256) lw[i]=((const float4*)g_l3t)[i];
  __syncthreads();
  int v=blockIdx.x*256+tid;
  float aS[32], aC[32];
#pragma unroll
  for(int c=0;c<32;c++){ aS[c]=0.f; aC[c]=0.f; }
  for(int ci=0;ci<64;ci++){
    float in=g_f3[ci*NV3+v];
#pragma unroll
    for(int j=0;j<8;j++){
      float4 w=lw[ci*8+j];
      kacc(aS[j*4+0],aC[j*4+0],in,w.x); kacc(aS[j*4+1],aC[j*4+1],in,w.y);
      kacc(aS[j*4+2],aC[j*4+2],in,w.z); kacc(aS[j*4+3],aC[j*4+3],in,w.w);
    }
  }
  float mx=-1e30f;
#pragma unroll
  for(int c=0;c<32;c++){
    float pv=__fadd_rn(kfin(aS[c],aC[c]),__ldg(&b[c]));
    g_p3[c*NV3+v]=pv; mx=fmaxf(mx,pv);
  }
  g_s3[v]=mx;
}

__global__ void p2_k(const float* __restrict__ b){
  __shared__ float4 lw[256];
  int tid=threadIdx.x;
  for(int i=tid;i<256;i+=256) lw[i]=((const float4*)g_l2t)[i];
  __syncthreads();
  int v=blockIdx.x*256+tid;
  int z=v/(H2*W2); int r=v%(H2*W2); int y=r/W2; int xx=r%W2;
  int v3=((z>>1)*H3+(y>>1))*W3+(xx>>1);
  float aS[32], aC[32];
#pragma unroll
  for(int c=0;c<32;c++){ aS[c]=0.f; aC[c]=0.f; }
  for(int ci=0;ci<32;ci++){
    float in=g_f2[ci*NV2+v];
#pragma unroll
    for(int j=0;j<8;j++){
      float4 w=lw[ci*8+j];
      kacc(aS[j*4+0],aC[j*4+0],in,w.x); kacc(aS[j*4+1],aC[j*4+1],in,w.y);
      kacc(aS[j*4+2],aC[j*4+2],in,w.z); kacc(aS[j*4+3],aC[j*4+3],in,w.w);
    }
  }
  float mx=-1e30f;
#pragma unroll
  for(int c=0;c<32;c++){
    float pv=__fadd_rn(__fadd_rn(kfin(aS[c],aC[c]),__ldg(&b[c])), g_p3[c*NV3+v3]);
    g_p2[c*NV2+v]=pv; mx=fmaxf(mx,pv);
  }
  g_s2[v]=mx;
}

__global__ void p1_k(const float* __restrict__ b){
  __shared__ float4 lw[128];
  int tid=threadIdx.x;
  if(tid<128) lw[tid]=((const float4*)g_l1t)[tid];
  __syncthreads();
  int v=blockIdx.x*256+tid;
  int z=v/(H1*W1); int r=v%(H1*W1); int y=r/W1; int xx=r%W1;
  int v2=((z>>1)*H2+(y>>1))*W2+(xx>>1);
  float aS[32], aC[32];
#pragma unroll
  for(int c=0;c<32;c++){ aS[c]=0.f; aC[c]=0.f; }
  for(int ci=0;ci<16;ci++){
    float in=g_f1[ci*NV1+v];
#pragma unroll
    for(int j=0;j<8;j++){
      float4 w=lw[ci*8+j];
      kacc(aS[j*4+0],aC[j*4+0],in,w.x); kacc(aS[j*4+1],aC[j*4+1],in,w.y);
      kacc(aS[j*4+2],aC[j*4+2],in,w.z); kacc(aS[j*4+3],aC[j*4+3],in,w.w);
    }
  }
  float mx=-1e30f;
#pragma unroll
  for(int c=0;c<32;c++){
    float pv=__fadd_rn(__fadd_rn(kfin(aS[c],aC[c]),__ldg(&b[c])), g_p2[c*NV2+v2]);
    g_p1[c*NV1+v]=pv; mx=fmaxf(mx,pv);
  }
  g_s1[v]=mx;
}

// ------------------------------------------------------------------
// exact top-K=512: radix threshold select + stable bitonic sort
// ------------------------------------------------------------------
__device__ __forceinline__ unsigned okey(float f){
  unsigned u=__float_as_uint(f);
  return (u & 0x80000000u) ? ~u : (u | 0x80000000u);
}
__device__ __forceinline__ float fromkey(unsigned k){
  unsigned u = (k & 0x80000000u) ? (k ^ 0x80000000u) : ~k;
  return __uint_as_float(u);
}
__device__ __forceinline__ const float* level_score(int l){
  return (l==0)? g_s1 : (l==1)? g_s2 : g_s3;
}

__global__ void tk_clear(){
  int t=blockIdx.x*256+threadIdx.x;
  if(t<65536) g_hist16[t]=0;
  if(t<256) g_hist8[t]=0;
  if(t<8) g_ctrl[t]=0;
}
__global__ void tk_hist16(int l,int N){
  int t=blockIdx.x*256+threadIdx.x; if(t>=N)return;
  atomicAdd(&g_hist16[okey(level_score(l)[t])>>16],1u);
}
__global__ void tk_find16(){
  __shared__ unsigned part[256];
  int t=threadIdx.x;
  unsigned sm=0;
  for(int i=0;i<256;i++) sm+=g_hist16[t*256+i];
  part[t]=sm;
  __syncthreads();
  if(t==0){
    unsigned cum=0;
    for(int c=255;c>=0;c--){
      if(cum+part[c]>=K_TOP){
        for(int bb=c*256+255;;bb--){
          unsigned h=g_hist16[bb];
          if(cum+h>=K_TOP){ g_ctrl[0]=bb; g_ctrl[1]=(int)cum; break; }
          cum+=h;
        }
        break;
      }
      cum+=part[c];
    }
  }
}
__global__ void tk_hist8(int l,int N){
  int t=blockIdx.x*256+threadIdx.x; if(t>=N)return;
  unsigned k=okey(level_score(l)[t]);
  if((int)(k>>16)==g_ctrl[0]) atomicAdd(&g_hist8[(k>>8)&255],1u);
}
__global__ void tk_find8(){
  unsigned cum=(unsigned)g_ctrl[1];
  int b16=g_ctrl[0];
  for(int bb=255;bb>=0;bb--){
    unsigned h=g_hist8[bb];
    if(cum+h>=K_TOP){ g_ctrl[2]=(b16<<8)|bb; break; }
    cum+=h;
  }
}
__global__ void tk_gather(int l,int N){
  int t=blockIdx.x*256+threadIdx.x; if(t>=N)return;
  unsigned k=okey(level_score(l)[t]);
  if((int)(k>>8) >= g_ctrl[2]){
    int pos=atomicAdd(&g_ctrl[3],1);
    if(pos<CAP){ g_candKey[pos]=k; g_candIdx[pos]=t; }
  }
}
__global__ void tk_sort(int level){
  __shared__ unsigned long long a[CAP];
  int t=threadIdx.x;
  int M=min(g_ctrl[3],CAP);
  for(int i=t;i<CAP;i+=1024)
    a[i] = (i<M)? ((((unsigned long long)g_candKey[i])<<32) | (unsigned)(~g_candIdx[i])) : 0ULL;
  __syncthreads();
  for(int kk=2;kk<=CAP;kk<<=1){
    for(int j=kk>>1;j>0;j>>=1){
      for(int i=t;i<CAP;i+=1024){
        int ixj=i^j;
        if(ixj>i){
          bool asc=((i&kk)!=0);          // descending overall
          unsigned long long A=a[i],B=a[ixj];
          if(asc? (A>B):(A<B)){ a[i]=B; a[ixj]=A; }
        }
      }
      __syncthreads();
    }
  }
  if(t<K_TOP){
    unsigned long long c=a[t];
    g_topval[level*K_TOP+t]=fromkey((unsigned)(c>>32));
    g_topidx[level*K_TOP+t]=~((unsigned)c);
  }
}

// ------------------------------------------------------------------
// per-candidate: cube mean/std (fp64) -> MLP (fp64 accum) -> output
// ------------------------------------------------------------------
__global__ void mlp_k(const float* __restrict__ w1,const float* __restrict__ b1,
                      const float* __restrict__ w2,const float* __restrict__ b2,
                      float* __restrict__ out){
  int l=blockIdx.y; int slot=blockIdx.x; int t=threadIdx.x;
  __shared__ float feat[64];
  __shared__ float h[128];
  int D,H,W; const float* p;
  if(l==0){D=D1;H=H1;W=W1;p=g_p1;}
  else if(l==1){D=D2;H=H2;W=W2;p=g_p2;}
  else {D=D3;H=H3;W=W3;p=g_p3;}
  unsigned idx=g_topidx[l*K_TOP+slot];
  float val=g_topval[l*K_TOP+slot];
  int plane=D*H*W;
  int z=(int)idx/(H*W); int r=(int)idx%(H*W); int y=r/W; int xx=r%W;
  int zs=min(max(z-2,0),D-4);
  int ys=min(max(y-2,0),H-4);
  int xs=min(max(xx-2,0),W-4);
  if(t<32){
    float cv[64];
    const float* base = p + t*plane + (zs*H+ys)*W + xs;
#pragma unroll
    for(int dz=0;dz<4;dz++)
#pragma unroll
      for(int dy=0;dy<4;dy++)
#pragma unroll
        for(int dx=0;dx<4;dx++)
          cv[(dz*4+dy)*4+dx]=base[(dz*H+dy)*W+dx];
    double s=0.0;
#pragma unroll
    for(int i=0;i<64;i++) s+=(double)cv[i];
    double m=s*(1.0/64.0);
    double ss=0.0;
#pragma unroll
    for(int i=0;i<64;i++){ double d=(double)cv[i]-m; ss+=d*d; }
    double var=ss*(1.0/64.0);
    feat[t]=(float)m;
    feat[32+t]=(float)sqrt(var+1e-6);
  }
  __syncthreads();
  {
    double acc=0.0;
    for(int i=0;i<64;i++) acc += (double)feat[i]*(double)__ldg(&w1[i*128+t]);
    h[t]=fmaxf((float)(acc+(double)__ldg(&b1[t])),0.f);
  }
  __syncthreads();
  if(t<2){
    double acc=0.0;
    for(int j=0;j<128;j++) acc+=(double)h[j]*(double)__ldg(&w2[j*2+t]);
    float valid=(val>0.5f)?1.f:0.f;
    out[(l*K_TOP+slot)*2+t]=(float)(acc+(double)__ldg(&b2[t]))*valid;
  }
}

// ------------------------------------------------------------------
extern "C" void kernel_launch(void* const* d_in, const int* in_sizes, int n_in,
                              void* d_out, int out_size){
  const float* x  =(const float*)d_in[0];
  const float* c1w=(const float*)d_in[1];  const float* c1b=(const float*)d_in[2];
  const float* c2w=(const float*)d_in[3];  const float* c2b=(const float*)d_in[4];
  const float* c3w=(const float*)d_in[5];  const float* c3b=(const float*)d_in[6];
  const float* l1w=(const float*)d_in[7];  const float* l1b=(const float*)d_in[8];
  const float* l2w=(const float*)d_in[9];  const float* l2b=(const float*)d_in[10];
  const float* l3w=(const float*)d_in[11]; const float* l3b=(const float*)d_in[12];
  const float* w1 =(const float*)d_in[13]; const float* b1 =(const float*)d_in[14];
  const float* w2 =(const float*)d_in[15]; const float* b2 =(const float*)d_in[16];
  float* out=(float*)d_out;

  prep_k<<<216,256>>>(c1w,c2w,c3w,l1w,l2w,l3w);
  conv1_k<<<NV1/256,256>>>(x,c1b);
  conv2_k<<<NV2/256,256>>>(c2b);
  conv3_k<<<432,256>>>(c3b);
  p3_k<<<NV3/256,256>>>(l3b);
  p2_k<<<NV2/256,256>>>(l2b);
  p1_k<<<NV1/256,256>>>(l1b);

  const int Ns[3]={NV1,NV2,NV3};
  for(int l=0;l<3;l++){
    int N=Ns[l];
    int nb=(N+255)/256;
    tk_clear<<<256,256>>>();
    tk_hist16<<<nb,256>>>(l,N);
    tk_find16<<<1,256>>>();
    tk_hist8<<<nb,256>>>(l,N);
    tk_find8<<<1,1>>>();
    tk_gather<<<nb,256>>>(l,N);
    tk_sort<<<1,1024>>>(l);
  }

  mlp_k<<<dim3(K_TOP,3),128>>>(w1,b1,w2,b2,out);
}

// round 6
// speedup vs baseline: 1.4081x; 1.4081x over previous
#include <cuda_runtime.h>
#include <math.h>

#define K_TOP 512
#define CAP 4096

// level dims
#define D1 48
#define H1 96
#define W1 96
#define NV1 (D1*H1*W1)   // 442368
#define D2 24
#define H2 48
#define W2 48
#define NV2 (D2*H2*W2)   // 55296
#define D3 12
#define H3 24
#define W3 24
#define NV3 (D3*H3*W3)   // 6912

// ------------------------------------------------------------------
// 4-op fused Kahan: product + compensation subtract folded into FMA.
// Error stays O(1 ulp) independent of term count/order.
// Final value = s - c.
// ------------------------------------------------------------------
__device__ __forceinline__ void kacc4(float& s, float& c, float a, float b){
  float y = __fmaf_rn(a,b,-c);
  float t = __fadd_rn(s,y);
  c = __fsub_rn(__fsub_rn(t,s),y);
  s = t;
}
__device__ __forceinline__ float kfin4(float s, float c){
  return __fsub_rn(s,c);
}

// 7-op TwoProd+TwoSum (exact) - kept for the score-critical lateral sums
__device__ __forceinline__ void kacc(float& s, float& c, float a, float b){
  float p = __fmul_rn(a,b);
  float e = __fmaf_rn(a,b,-p);
  float t = __fadd_rn(s,p);
  float z = __fsub_rn(t,s);
  float err = __fadd_rn(__fsub_rn(s,__fsub_rn(t,z)), __fsub_rn(p,z));
  s = t;
  c = __fadd_rn(c, __fadd_rn(err,e));
}
__device__ __forceinline__ float kfin(float s, float c){
  return (float)((double)s + (double)c);
}

// ------------------------------------------------------------------
// scratch (static __device__, no runtime allocation)
// ------------------------------------------------------------------
__device__ float g_f1[16*NV1];
__device__ float g_f2[32*NV2];
__device__ float g_f3[64*NV3];
__device__ float g_p1[32*NV1];
__device__ float g_p2[32*NV2];
__device__ float g_p3[32*NV3];
__device__ float g_s1[NV1];
__device__ float g_s2[NV2];
__device__ float g_s3[NV3];
__device__ float g_c1t[432];      // [k27][o16]
__device__ float g_c2t[13824];    // [k27][ci16][o32]
__device__ float g_c3t[55296];    // [k27][ci32][o64]
__device__ float g_l1t[512];      // [ci16][c32]
__device__ float g_l2t[1024];     // [ci32][c32]
__device__ float g_l3t[2048];     // [ci64][c32]
__device__ unsigned g_hist16[65536];
__device__ unsigned g_hist8[256];
__device__ int g_ctrl[8];         // [0]=b16 [1]=cntAbove16 [2]=thresh24 [3]=candCount
__device__ unsigned g_candKey[CAP];
__device__ unsigned g_candIdx[CAP];
__device__ float g_topval[3*K_TOP];
__device__ unsigned g_topidx[3*K_TOP];

// ------------------------------------------------------------------
// weight transposition (once per launch; cheap)
// ------------------------------------------------------------------
__global__ void prep_k(const float* __restrict__ c1w, const float* __restrict__ c2w,
                       const float* __restrict__ c3w, const float* __restrict__ l1w,
                       const float* __restrict__ l2w, const float* __restrict__ l3w){
  int t = blockIdx.x*blockDim.x + threadIdx.x;
  if (t < 432){ int k=t/16, o=t%16; g_c1t[t] = c1w[o*27+k]; }
  if (t < 13824){ int k=t/512; int ci=(t>>5)&15; int o=t&31; g_c2t[t]=c2w[(o*16+ci)*27+k]; }
  if (t < 55296){ int k=t/2048; int ci=(t>>6)&31; int o=t&63; g_c3t[t]=c3w[(o*32+ci)*27+k]; }
  if (t < 512){ int ci=t/32, c=t%32; g_l1t[t]=l1w[c*16+ci]; }
  if (t < 1024){ int ci=t/32, c=t%32; g_l2t[t]=l2w[c*32+ci]; }
  if (t < 2048){ int ci=t/32, c=t%32; g_l3t[t]=l3w[c*64+ci]; }
}

// ------------------------------------------------------------------
// conv1: [1,96,192,192] -> relu -> f1 [16,48,96,96], 3x3x3 s2 SAME
// ------------------------------------------------------------------
__global__ void conv1_k(const float* __restrict__ x, const float* __restrict__ b){
  __shared__ float4 ws[108];
  __shared__ float bs[16];
  int tid = threadIdx.x;
  if (tid < 108) ws[tid] = ((const float4*)g_c1t)[tid];
  if (tid < 16) bs[tid] = b[tid];
  __syncthreads();
  int v = blockIdx.x*256 + tid;
  int z = v / (H1*W1); int r = v % (H1*W1); int y = r / W1; int xx = r % W1;
  float aS[16], aC[16];
#pragma unroll
  for (int o=0;o<16;o++){ aS[o]=0.f; aC[o]=0.f; }
#pragma unroll
  for (int kd=0;kd<3;kd++){
    int iz=2*z+kd; bool okz = iz<96;
#pragma unroll
    for (int kh=0;kh<3;kh++){
      int iy=2*y+kh; bool oky = iy<192;
#pragma unroll
      for (int kw=0;kw<3;kw++){
        int ix=2*xx+kw;
        if (okz && oky && ix<192){
          float in = __ldg(&x[(iz*192+iy)*192+ix]);
          int k=(kd*3+kh)*3+kw;
#pragma unroll
          for (int j=0;j<4;j++){
            float4 w = ws[k*4+j];
            kacc4(aS[j*4+0],aC[j*4+0],in,w.x); kacc4(aS[j*4+1],aC[j*4+1],in,w.y);
            kacc4(aS[j*4+2],aC[j*4+2],in,w.z); kacc4(aS[j*4+3],aC[j*4+3],in,w.w);
          }
        }
      }
    }
  }
#pragma unroll
  for (int o=0;o<16;o++)
    g_f1[o*NV1+v] = fmaxf(__fadd_rn(kfin4(aS[o],aC[o]),bs[o]),0.f);
}

// ------------------------------------------------------------------
// conv2: f1 [16,48,96,96] -> relu -> f2 [32,24,48,48]
// 4-way output-channel split (8 oc per block) for occupancy;
// full 27-tap weight slab for the split staged once (13.8KB).
// ------------------------------------------------------------------
__global__ void conv2_k(const float* __restrict__ b){
  __shared__ float ws[3456];   // [k27][ci16][o8]
  int s = blockIdx.y;          // oc split 0..3
  int tid=threadIdx.x;
  for(int i=tid;i<3456;i+=256){
    int k=i>>7; int rr=i&127; int ci=rr>>3; int oo=rr&7;
    ws[i]=g_c2t[k*512+ci*32+s*8+oo];
  }
  __syncthreads();
  int v = blockIdx.x*256+tid;
  int z=v/(H2*W2); int r=v%(H2*W2); int y=r/W2; int xx=r%W2;
  float aS[8], aC[8];
#pragma unroll
  for(int o=0;o<8;o++){ aS[o]=0.f; aC[o]=0.f; }
#pragma unroll
  for(int kd=0;kd<3;kd++){
    int iz=2*z+kd; bool okz=iz<D1;
#pragma unroll
    for(int kh=0;kh<3;kh++){
      int iy=2*y+kh; bool oky=iy<H1;
#pragma unroll
      for(int kw=0;kw<3;kw++){
        int ix=2*xx+kw;
        if(okz && oky && ix<W1){
          int off=(iz*H1+iy)*W1+ix;
          int kl=(kd*3+kh)*3+kw;
#pragma unroll
          for(int ci=0;ci<16;ci++){
            float in=__ldg(&g_f1[ci*NV1+off]);
            const float4* wr=(const float4*)&ws[(kl*16+ci)*8];
            float4 w0=wr[0], w1=wr[1];
            kacc4(aS[0],aC[0],in,w0.x); kacc4(aS[1],aC[1],in,w0.y);
            kacc4(aS[2],aC[2],in,w0.z); kacc4(aS[3],aC[3],in,w0.w);
            kacc4(aS[4],aC[4],in,w1.x); kacc4(aS[5],aC[5],in,w1.y);
            kacc4(aS[6],aC[6],in,w1.z); kacc4(aS[7],aC[7],in,w1.w);
          }
        }
      }
    }
  }
#pragma unroll
  for(int o=0;o<8;o++){
    int c=s*8+o;
    g_f2[c*NV2+v]=fmaxf(__fadd_rn(kfin4(aS[o],aC[o]),__ldg(&b[c])),0.f);
  }
}

// ------------------------------------------------------------------
// conv3: f2 [32,24,48,48] -> relu -> f3 [64,12,24,24]
// ------------------------------------------------------------------
__global__ void conv3_k(const float* __restrict__ b){
  __shared__ float4 ws[1024];   // 2 taps * 32ci * 16 float4 = 16KB
  __shared__ float shin[7200];  // 32ci * 5*5*9 = 28.8KB
  int tid=threadIdx.x;
  int bt=blockIdx.x;
  int btz=bt/72; int rem=bt%72; int bty=rem/6; int btx=rem%6;
  int og=tid&15; int vi=tid>>4;
  int vz=vi>>3; int vy=(vi>>2)&1; int vx=vi&3;
  int z0=btz*4, y0=bty*4, x0=btx*8;
  for(int i=tid;i<7200;i+=256){
    int cl=i/225; int r=i%225; int lz=r/45; int r2=r%45; int ly=r2/9; int lx=r2%9;
    int gz=z0+lz, gy=y0+ly, gx=x0+lx;
    shin[i]=(gz<D2&&gy<H2&&gx<W2)? g_f2[cl*NV2+(gz*H2+gy)*W2+gx] : 0.f;
  }
  float aS[4]={0.f,0.f,0.f,0.f}, aC[4]={0.f,0.f,0.f,0.f};
  int sbase=(2*vz)*45+(2*vy)*9+(2*vx);
  for(int ph=0; ph<14; ph++){
    int ktaps=(ph==13)?1:2;
    __syncthreads();
    for(int i=tid;i<ktaps*2048;i+=256) ((float*)ws)[i]=g_c3t[ph*4096+i];
    __syncthreads();
    for(int kl=0;kl<ktaps;kl++){
      int k=ph*2+kl;
      int kd=k/9, kh=(k%9)/3, kw=k%3;
      const float* sh=&shin[sbase + kd*45 + kh*9 + kw];
      const float4* wb=&ws[kl*512+og];
#pragma unroll
      for(int ci=0;ci<32;ci++){
        float in=sh[ci*225];
        float4 w=wb[ci*16];
        kacc4(aS[0],aC[0],in,w.x); kacc4(aS[1],aC[1],in,w.y);
        kacc4(aS[2],aC[2],in,w.z); kacc4(aS[3],aC[3],in,w.w);
      }
    }
  }
  int oz=btz*2+vz, oy=bty*2+vy, ox=btx*4+vx;
  int v=(oz*H3+oy)*W3+ox;
#pragma unroll
  for(int j=0;j<4;j++){
    int c=og*4+j;
    g_f3[c*NV3+v]=fmaxf(__fadd_rn(kfin4(aS[j],aC[j]),__ldg(&b[c])),0.f);
  }
}

// ------------------------------------------------------------------
// FPN laterals + top-down adds + per-voxel channel-max score
// score-critical: keep exact 7-op TwoSum here.
// ------------------------------------------------------------------
__global__ void p3_k(const float* __restrict__ b){
  __shared__ float4 lw[512];
  int tid=threadIdx.x;
  for(int i=tid;i<512;i+=256) lw[i]=((const float4*)g_l3t)[i];
  __syncthreads();
  int v=blockIdx.x*256+tid;
  float aS[32], aC[32];
#pragma unroll
  for(int c=0;c<32;c++){ aS[c]=0.f; aC[c]=0.f; }
  for(int ci=0;ci<64;ci++){
    float in=g_f3[ci*NV3+v];
#pragma unroll
    for(int j=0;j<8;j++){
      float4 w=lw[ci*8+j];
      kacc(aS[j*4+0],aC[j*4+0],in,w.x); kacc(aS[j*4+1],aC[j*4+1],in,w.y);
      kacc(aS[j*4+2],aC[j*4+2],in,w.z); kacc(aS[j*4+3],aC[j*4+3],in,w.w);
    }
  }
  float mx=-1e30f;
#pragma unroll
  for(int c=0;c<32;c++){
    float pv=__fadd_rn(kfin(aS[c],aC[c]),__ldg(&b[c]));
    g_p3[c*NV3+v]=pv; mx=fmaxf(mx,pv);
  }
  g_s3[v]=mx;
}

__global__ void p2_k(const float* __restrict__ b){
  __shared__ float4 lw[256];
  int tid=threadIdx.x;
  for(int i=tid;i<256;i+=256) lw[i]=((const float4*)g_l2t)[i];
  __syncthreads();
  int v=blockIdx.x*256+tid;
  int z=v/(H2*W2); int r=v%(H2*W2); int y=r/W2; int xx=r%W2;
  int v3=((z>>1)*H3+(y>>1))*W3+(xx>>1);
  float aS[32], aC[32];
#pragma unroll
  for(int c=0;c<32;c++){ aS[c]=0.f; aC[c]=0.f; }
  for(int ci=0;ci<32;ci++){
    float in=g_f2[ci*NV2+v];
#pragma unroll
    for(int j=0;j<8;j++){
      float4 w=lw[ci*8+j];
      kacc(aS[j*4+0],aC[j*4+0],in,w.x); kacc(aS[j*4+1],aC[j*4+1],in,w.y);
      kacc(aS[j*4+2],aC[j*4+2],in,w.z); kacc(aS[j*4+3],aC[j*4+3],in,w.w);
    }
  }
  float mx=-1e30f;
#pragma unroll
  for(int c=0;c<32;c++){
    float pv=__fadd_rn(__fadd_rn(kfin(aS[c],aC[c]),__ldg(&b[c])), g_p3[c*NV3+v3]);
    g_p2[c*NV2+v]=pv; mx=fmaxf(mx,pv);
  }
  g_s2[v]=mx;
}

__global__ void p1_k(const float* __restrict__ b){
  __shared__ float4 lw[128];
  int tid=threadIdx.x;
  if(tid<128) lw[tid]=((const float4*)g_l1t)[tid];
  __syncthreads();
  int v=blockIdx.x*256+tid;
  int z=v/(H1*W1); int r=v%(H1*W1); int y=r/W1; int xx=r%W1;
  int v2=((z>>1)*H2+(y>>1))*W2+(xx>>1);
  float aS[32], aC[32];
#pragma unroll
  for(int c=0;c<32;c++){ aS[c]=0.f; aC[c]=0.f; }
  for(int ci=0;ci<16;ci++){
    float in=g_f1[ci*NV1+v];
#pragma unroll
    for(int j=0;j<8;j++){
      float4 w=lw[ci*8+j];
      kacc(aS[j*4+0],aC[j*4+0],in,w.x); kacc(aS[j*4+1],aC[j*4+1],in,w.y);
      kacc(aS[j*4+2],aC[j*4+2],in,w.z); kacc(aS[j*4+3],aC[j*4+3],in,w.w);
    }
  }
  float mx=-1e30f;
#pragma unroll
  for(int c=0;c<32;c++){
    float pv=__fadd_rn(__fadd_rn(kfin(aS[c],aC[c]),__ldg(&b[c])), g_p2[c*NV2+v2]);
    g_p1[c*NV1+v]=pv; mx=fmaxf(mx,pv);
  }
  g_s1[v]=mx;
}

// ------------------------------------------------------------------
// exact top-K=512: radix threshold select + stable bitonic sort
// ------------------------------------------------------------------
__device__ __forceinline__ unsigned okey(float f){
  unsigned u=__float_as_uint(f);
  return (u & 0x80000000u) ? ~u : (u | 0x80000000u);
}
__device__ __forceinline__ float fromkey(unsigned k){
  unsigned u = (k & 0x80000000u) ? (k ^ 0x80000000u) : ~k;
  return __uint_as_float(u);
}
__device__ __forceinline__ const float* level_score(int l){
  return (l==0)? g_s1 : (l==1)? g_s2 : g_s3;
}

__global__ void tk_clear(){
  int t=blockIdx.x*256+threadIdx.x;
  if(t<65536) g_hist16[t]=0;
  if(t<256) g_hist8[t]=0;
  if(t<8) g_ctrl[t]=0;
}
__global__ void tk_hist16(int l,int N){
  int t=blockIdx.x*256+threadIdx.x; if(t>=N)return;
  atomicAdd(&g_hist16[okey(level_score(l)[t])>>16],1u);
}
__global__ void tk_find16(){
  __shared__ unsigned part[256];
  int t=threadIdx.x;
  unsigned sm=0;
  for(int i=0;i<256;i++) sm+=g_hist16[t*256+i];
  part[t]=sm;
  __syncthreads();
  if(t==0){
    unsigned cum=0;
    for(int c=255;c>=0;c--){
      if(cum+part[c]>=K_TOP){
        for(int bb=c*256+255;;bb--){
          unsigned h=g_hist16[bb];
          if(cum+h>=K_TOP){ g_ctrl[0]=bb; g_ctrl[1]=(int)cum; break; }
          cum+=h;
        }
        break;
      }
      cum+=part[c];
    }
  }
}
__global__ void tk_hist8(int l,int N){
  int t=blockIdx.x*256+threadIdx.x; if(t>=N)return;
  unsigned k=okey(level_score(l)[t]);
  if((int)(k>>16)==g_ctrl[0]) atomicAdd(&g_hist8[(k>>8)&255],1u);
}
__global__ void tk_find8(){
  unsigned cum=(unsigned)g_ctrl[1];
  int b16=g_ctrl[0];
  for(int bb=255;bb>=0;bb--){
    unsigned h=g_hist8[bb];
    if(cum+h>=K_TOP){ g_ctrl[2]=(b16<<8)|bb; break; }
    cum+=h;
  }
}
__global__ void tk_gather(int l,int N){
  int t=blockIdx.x*256+threadIdx.x; if(t>=N)return;
  unsigned k=okey(level_score(l)[t]);
  if((int)(k>>8) >= g_ctrl[2]){
    int pos=atomicAdd(&g_ctrl[3],1);
    if(pos<CAP){ g_candKey[pos]=k; g_candIdx[pos]=t; }
  }
}
__global__ void tk_sort(int level){
  __shared__ unsigned long long a[CAP];
  int t=threadIdx.x;
  int M=min(g_ctrl[3],CAP);
  for(int i=t;i<CAP;i+=1024)
    a[i] = (i<M)? ((((unsigned long long)g_candKey[i])<<32) | (unsigned)(~g_candIdx[i])) : 0ULL;
  __syncthreads();
  for(int kk=2;kk<=CAP;kk<<=1){
    for(int j=kk>>1;j>0;j>>=1){
      for(int i=t;i<CAP;i+=1024){
        int ixj=i^j;
        if(ixj>i){
          bool asc=((i&kk)!=0);          // descending overall
          unsigned long long A=a[i],B=a[ixj];
          if(asc? (A>B):(A<B)){ a[i]=B; a[ixj]=A; }
        }
      }
      __syncthreads();
    }
  }
  if(t<K_TOP){
    unsigned long long c=a[t];
    g_topval[level*K_TOP+t]=fromkey((unsigned)(c>>32));
    g_topidx[level*K_TOP+t]=~((unsigned)c);
  }
}

// ------------------------------------------------------------------
// per-candidate: cube mean/std (fp64) -> MLP (fp64 accum) -> output
// ------------------------------------------------------------------
__global__ void mlp_k(const float* __restrict__ w1,const float* __restrict__ b1,
                      const float* __restrict__ w2,const float* __restrict__ b2,
                      float* __restrict__ out){
  int l=blockIdx.y; int slot=blockIdx.x; int t=threadIdx.x;
  __shared__ float feat[64];
  __shared__ float h[128];
  int D,H,W; const float* p;
  if(l==0){D=D1;H=H1;W=W1;p=g_p1;}
  else if(l==1){D=D2;H=H2;W=W2;p=g_p2;}
  else {D=D3;H=H3;W=W3;p=g_p3;}
  unsigned idx=g_topidx[l*K_TOP+slot];
  float val=g_topval[l*K_TOP+slot];
  int plane=D*H*W;
  int z=(int)idx/(H*W); int r=(int)idx%(H*W); int y=r/W; int xx=r%W;
  int zs=min(max(z-2,0),D-4);
  int ys=min(max(y-2,0),H-4);
  int xs=min(max(xx-2,0),W-4);
  if(t<32){
    float cv[64];
    const float* base = p + t*plane + (zs*H+ys)*W + xs;
#pragma unroll
    for(int dz=0;dz<4;dz++)
#pragma unroll
      for(int dy=0;dy<4;dy++)
#pragma unroll
        for(int dx=0;dx<4;dx++)
          cv[(dz*4+dy)*4+dx]=base[(dz*H+dy)*W+dx];
    double s=0.0;
#pragma unroll
    for(int i=0;i<64;i++) s+=(double)cv[i];
    double m=s*(1.0/64.0);
    double ss=0.0;
#pragma unroll
    for(int i=0;i<64;i++){ double d=(double)cv[i]-m; ss+=d*d; }
    double var=ss*(1.0/64.0);
    feat[t]=(float)m;
    feat[32+t]=(float)sqrt(var+1e-6);
  }
  __syncthreads();
  {
    double acc=0.0;
    for(int i=0;i<64;i++) acc += (double)feat[i]*(double)__ldg(&w1[i*128+t]);
    h[t]=fmaxf((float)(acc+(double)__ldg(&b1[t])),0.f);
  }
  __syncthreads();
  if(t<2){
    double acc=0.0;
    for(int j=0;j<128;j++) acc+=(double)h[j]*(double)__ldg(&w2[j*2+t]);
    float valid=(val>0.5f)?1.f:0.f;
    out[(l*K_TOP+slot)*2+t]=(float)(acc+(double)__ldg(&b2[t]))*valid;
  }
}

// ------------------------------------------------------------------
extern "C" void kernel_launch(void* const* d_in, const int* in_sizes, int n_in,
                              void* d_out, int out_size){
  const float* x  =(const float*)d_in[0];
  const float* c1w=(const float*)d_in[1];  const float* c1b=(const float*)d_in[2];
  const float* c2w=(const float*)d_in[3];  const float* c2b=(const float*)d_in[4];
  const float* c3w=(const float*)d_in[5];  const float* c3b=(const float*)d_in[6];
  const float* l1w=(const float*)d_in[7];  const float* l1b=(const float*)d_in[8];
  const float* l2w=(const float*)d_in[9];  const float* l2b=(const float*)d_in[10];
  const float* l3w=(const float*)d_in[11]; const float* l3b=(const float*)d_in[12];
  const float* w1 =(const float*)d_in[13]; const float* b1 =(const float*)d_in[14];
  const float* w2 =(const float*)d_in[15]; const float* b2 =(const float*)d_in[16];
  float* out=(float*)d_out;

  prep_k<<<216,256>>>(c1w,c2w,c3w,l1w,l2w,l3w);
  conv1_k<<<NV1/256,256>>>(x,c1b);
  conv2_k<<<dim3(NV2/256,4),256>>>(c2b);
  conv3_k<<<432,256>>>(c3b);
  p3_k<<<NV3/256,256>>>(l3b);
  p2_k<<<NV2/256,256>>>(l2b);
  p1_k<<<NV1/256,256>>>(l1b);

  const int Ns[3]={NV1,NV2,NV3};
  for(int l=0;l<3;l++){
    int N=Ns[l];
    int nb=(N+255)/256;
    tk_clear<<<256,256>>>();
    tk_hist16<<<nb,256>>>(l,N);
    tk_find16<<<1,256>>>();
    tk_hist8<<<nb,256>>>(l,N);
    tk_find8<<<1,1>>>();
    tk_gather<<<nb,256>>>(l,N);
    tk_sort<<<1,1024>>>(l);
  }

  mlp_k<<<dim3(K_TOP,3),128>>>(w1,b1,w2,b2,out);
}

// round 8
// speedup vs baseline: 2.2169x; 1.5744x over previous
#include <cuda_runtime.h>
#include <math.h>

#define K_TOP 512
#define CAP 4096

// level dims
#define D1 48
#define H1 96
#define W1 96
#define NV1 (D1*H1*W1)   // 442368
#define D2 24
#define H2 48
#define W2 48
#define NV2 (D2*H2*W2)   // 55296
#define D3 12
#define H3 24
#define W3 24
#define NV3 (D3*H3*W3)   // 6912

typedef unsigned long long u64;

// ------------------------------------------------------------------
// packed f32x2 primitives (sm_103a FFMA2 path)
// ------------------------------------------------------------------
__device__ __forceinline__ u64 bcast2(float a){
  u64 r; asm("mov.b64 %0, {%1, %1};" : "=l"(r) : "f"(a)); return r;
}
__device__ __forceinline__ void unpack2(u64 v, float& lo, float& hi){
  asm("mov.b64 {%0, %1}, %2;" : "=f"(lo), "=f"(hi) : "l"(v));
}
__device__ __forceinline__ u64 fma2(u64 a, u64 b, u64 c){
  u64 r; asm("fma.rn.f32x2 %0, %1, %2, %3;" : "=l"(r) : "l"(a), "l"(b), "l"(c)); return r;
}
__device__ __forceinline__ u64 add2(u64 a, u64 b){
  u64 r; asm("add.rn.f32x2 %0, %1, %2;" : "=l"(r) : "l"(a), "l"(b)); return r;
}

#define NEG2 0xBF800000BF800000ULL   // {-1.f,-1.f}
#define MZ2  0x8000000080000000ULL   // {-0.f,-0.f}

// packed Kahan, compensation stored negated (cn = -c).
// Per-lane bit-identical to scalar: y=fma(a,b,-c); t=s+y; c=(t-s)-y; s=t.
__device__ __forceinline__ void kacc2(u64& s, u64& cn, u64 a, u64 b){
  u64 y = fma2(a, b, cn);
  u64 t = add2(s, y);
  u64 z = fma2(t, NEG2, s);     // RN(s - t)
  cn = add2(y, z);              // y - (t-s) = -c_new
  s = t;
}
__device__ __forceinline__ u64 kfin2(u64 s, u64 cn){ return add2(s, cn); }  // s - c

// ------------------------------------------------------------------
// scratch (static __device__, no runtime allocation)
// ------------------------------------------------------------------
__device__ float g_f1[16*NV1];
__device__ float g_f2[32*NV2];
__device__ float g_f3[64*NV3];
__device__ float g_p1[32*NV1];
__device__ float g_p2[32*NV2];
__device__ float g_p3[32*NV3];
__device__ float g_s1[NV1];
__device__ float g_s2[NV2];
__device__ float g_s3[NV3];
__device__ float g_c1t[432];      // [k27][o16]
__device__ float g_c2t[13824];    // [k27][ci16][o32]
__device__ float g_c3t[55296];    // [k27][ci32][o64]
__device__ float g_l1t[512];      // [ci16][c32]
__device__ float g_l2t[1024];     // [ci32][c32]
__device__ float g_l3t[2048];     // [ci64][c32]
__device__ unsigned g_hist16[3][65536];
__device__ unsigned g_hist8[3][256];
__device__ int g_ctrl[3][8];      // [0]=b16 [1]=cntAbove16 [2]=thresh24 [3]=candCount
__device__ unsigned g_candKey[3][CAP];
__device__ unsigned g_candIdx[3][CAP];
__device__ float g_topval[3*K_TOP];
__device__ unsigned g_topidx[3*K_TOP];

// ------------------------------------------------------------------
// weight transposition (once per launch; cheap)
// ------------------------------------------------------------------
__global__ void prep_k(const float* __restrict__ c1w, const float* __restrict__ c2w,
                       const float* __restrict__ c3w, const float* __restrict__ l1w,
                       const float* __restrict__ l2w, const float* __restrict__ l3w){
  int t = blockIdx.x*blockDim.x + threadIdx.x;
  if (t < 432){ int k=t/16, o=t%16; g_c1t[t] = c1w[o*27+k]; }
  if (t < 13824){ int k=t/512; int ci=(t>>5)&15; int o=t&31; g_c2t[t]=c2w[(o*16+ci)*27+k]; }
  if (t < 55296){ int k=t/2048; int ci=(t>>6)&31; int o=t&63; g_c3t[t]=c3w[(o*32+ci)*27+k]; }
  if (t < 512){ int ci=t/32, c=t%32; g_l1t[t]=l1w[c*16+ci]; }
  if (t < 1024){ int ci=t/32, c=t%32; g_l2t[t]=l2w[c*32+ci]; }
  if (t < 2048){ int ci=t/32, c=t%32; g_l3t[t]=l3w[c*64+ci]; }
}

// ------------------------------------------------------------------
// conv1: [1,96,192,192] -> relu -> f1 [16,48,96,96], 3x3x3 s2 SAME
// ------------------------------------------------------------------
__global__ void conv1_k(const float* __restrict__ x, const float* __restrict__ b){
  __shared__ float ws[432];
  __shared__ float bs[16];
  int tid = threadIdx.x;
  if (tid < 108) ((float4*)ws)[tid] = ((const float4*)g_c1t)[tid];
  if (tid < 16) bs[tid] = b[tid];
  __syncthreads();
  const u64* wsu = (const u64*)ws;
  int v = blockIdx.x*256 + tid;
  int z = v / (H1*W1); int r = v % (H1*W1); int y = r / W1; int xx = r % W1;
  u64 S[8], C[8];
#pragma unroll
  for (int j=0;j<8;j++){ S[j]=0ULL; C[j]=MZ2; }
#pragma unroll
  for (int kd=0;kd<3;kd++){
    int iz=2*z+kd; bool okz = iz<96;
#pragma unroll
    for (int kh=0;kh<3;kh++){
      int iy=2*y+kh; bool oky = iy<192;
#pragma unroll
      for (int kw=0;kw<3;kw++){
        int ix=2*xx+kw;
        if (okz && oky && ix<192){
          u64 in2 = bcast2(__ldg(&x[(iz*192+iy)*192+ix]));
          int k=(kd*3+kh)*3+kw;
#pragma unroll
          for (int j=0;j<8;j++) kacc2(S[j],C[j],in2,wsu[k*8+j]);
        }
      }
    }
  }
#pragma unroll
  for (int j=0;j<8;j++){
    float v0,v1; unpack2(kfin2(S[j],C[j]),v0,v1);
    g_f1[(2*j  )*NV1+v] = fmaxf(__fadd_rn(v0,bs[2*j  ]),0.f);
    g_f1[(2*j+1)*NV1+v] = fmaxf(__fadd_rn(v1,bs[2*j+1]),0.f);
  }
}

// ------------------------------------------------------------------
// conv2: f1 [16,48,96,96] -> relu -> f2 [32,24,48,48]
// 4-way oc split (8 oc/block); packed pairs.
// ------------------------------------------------------------------
__global__ void conv2_k(const float* __restrict__ b){
  __shared__ float ws[3456];   // [k27][ci16][o8]
  int s = blockIdx.y;          // oc split 0..3
  int tid=threadIdx.x;
  for(int i=tid;i<3456;i+=256){
    int k=i>>7; int rr=i&127; int ci=rr>>3; int oo=rr&7;
    ws[i]=g_c2t[k*512+ci*32+s*8+oo];
  }
  __syncthreads();
  const u64* wsu = (const u64*)ws;
  int v = blockIdx.x*256+tid;
  int z=v/(H2*W2); int r=v%(H2*W2); int y=r/W2; int xx=r%W2;
  u64 S[4], C[4];
#pragma unroll
  for(int j=0;j<4;j++){ S[j]=0ULL; C[j]=MZ2; }
#pragma unroll
  for(int kd=0;kd<3;kd++){
    int iz=2*z+kd; bool okz=iz<D1;
#pragma unroll
    for(int kh=0;kh<3;kh++){
      int iy=2*y+kh; bool oky=iy<H1;
#pragma unroll
      for(int kw=0;kw<3;kw++){
        int ix=2*xx+kw;
        if(okz && oky && ix<W1){
          int off=(iz*H1+iy)*W1+ix;
          int kl=(kd*3+kh)*3+kw;
#pragma unroll
          for(int ci=0;ci<16;ci++){
            u64 in2=bcast2(__ldg(&g_f1[ci*NV1+off]));
            const u64* wr=&wsu[(kl*16+ci)*4];
            kacc2(S[0],C[0],in2,wr[0]); kacc2(S[1],C[1],in2,wr[1]);
            kacc2(S[2],C[2],in2,wr[2]); kacc2(S[3],C[3],in2,wr[3]);
          }
        }
      }
    }
  }
#pragma unroll
  for(int j=0;j<4;j++){
    float v0,v1; unpack2(kfin2(S[j],C[j]),v0,v1);
    int c=s*8+2*j;
    g_f2[c*NV2+v]    =fmaxf(__fadd_rn(v0,__ldg(&b[c])),0.f);
    g_f2[(c+1)*NV2+v]=fmaxf(__fadd_rn(v1,__ldg(&b[c+1])),0.f);
  }
}

// ------------------------------------------------------------------
// conv3: f2 [32,24,48,48] -> relu -> f3 [64,12,24,24]
// 16-voxel tile x 16 og-groups (4 oc each, 2 packed pairs)
// ------------------------------------------------------------------
__global__ void conv3_k(const float* __restrict__ b){
  __shared__ float ws[4096];    // 2 taps * 32ci * 64oc
  __shared__ float shin[7200];  // 32ci * 5*5*9
  int tid=threadIdx.x;
  int bt=blockIdx.x;
  int btz=bt/72; int rem=bt%72; int bty=rem/6; int btx=rem%6;
  int og=tid&15; int vi=tid>>4;
  int vz=vi>>3; int vy=(vi>>2)&1; int vx=vi&3;
  int z0=btz*4, y0=bty*4, x0=btx*8;
  for(int i=tid;i<7200;i+=256){
    int cl=i/225; int r=i%225; int lz=r/45; int r2=r%45; int ly=r2/9; int lx=r2%9;
    int gz=z0+lz, gy=y0+ly, gx=x0+lx;
    shin[i]=(gz<D2&&gy<H2&&gx<W2)? g_f2[cl*NV2+(gz*H2+gy)*W2+gx] : 0.f;
  }
  const u64* wsu=(const u64*)ws;
  u64 S[2]={0ULL,0ULL}, C[2]={MZ2,MZ2};
  int sbase=(2*vz)*45+(2*vy)*9+(2*vx);
  for(int ph=0; ph<14; ph++){
    int ktaps=(ph==13)?1:2;
    __syncthreads();
    for(int i=tid;i<ktaps*2048;i+=256) ws[i]=g_c3t[ph*4096+i];
    __syncthreads();
    for(int kl=0;kl<ktaps;kl++){
      int k=ph*2+kl;
      int kd=k/9, kh=(k%9)/3, kw=k%3;
      const float* sh=&shin[sbase + kd*45 + kh*9 + kw];
      const u64* wb=&wsu[kl*1024 + og*2];   // FIX: tap stride is 1024 u64 (=2048 floats)
#pragma unroll
      for(int ci=0;ci<32;ci++){
        u64 in2=bcast2(sh[ci*225]);
        kacc2(S[0],C[0],in2,wb[ci*32]);
        kacc2(S[1],C[1],in2,wb[ci*32+1]);
      }
    }
  }
  int oz=btz*2+vz, oy=bty*2+vy, ox=btx*4+vx;
  int v=(oz*H3+oy)*W3+ox;
#pragma unroll
  for(int j=0;j<2;j++){
    float v0,v1; unpack2(kfin2(S[j],C[j]),v0,v1);
    int c=og*4+2*j;
    g_f3[c*NV3+v]    =fmaxf(__fadd_rn(v0,__ldg(&b[c])),0.f);
    g_f3[(c+1)*NV3+v]=fmaxf(__fadd_rn(v1,__ldg(&b[c+1])),0.f);
  }
}

// ------------------------------------------------------------------
// FPN laterals + top-down adds + per-voxel channel-max score
// packed Kahan (per-lane identical class to conv path)
// ------------------------------------------------------------------
__global__ void p3_k(const float* __restrict__ b){
  __shared__ float lw[2048];
  int tid=threadIdx.x;
  for(int i=tid;i<512;i+=256) ((float4*)lw)[i]=((const float4*)g_l3t)[i];
  __syncthreads();
  const u64* lwu=(const u64*)lw;
  int v=blockIdx.x*256+tid;
  u64 S[16], C[16];
#pragma unroll
  for(int j=0;j<16;j++){ S[j]=0ULL; C[j]=MZ2; }
  for(int ci=0;ci<64;ci++){
    u64 in2=bcast2(g_f3[ci*NV3+v]);
#pragma unroll
    for(int j=0;j<16;j++) kacc2(S[j],C[j],in2,lwu[ci*16+j]);
  }
  float mx=-1e30f;
#pragma unroll
  for(int j=0;j<16;j++){
    float v0,v1; unpack2(kfin2(S[j],C[j]),v0,v1);
    float p0=__fadd_rn(v0,__ldg(&b[2*j]));
    float p1=__fadd_rn(v1,__ldg(&b[2*j+1]));
    g_p3[(2*j)*NV3+v]=p0; g_p3[(2*j+1)*NV3+v]=p1;
    mx=fmaxf(mx,fmaxf(p0,p1));
  }
  g_s3[v]=mx;
}

__global__ void p2_k(const float* __restrict__ b){
  __shared__ float lw[1024];
  int tid=threadIdx.x;
  if(tid<256) ((float4*)lw)[tid]=((const float4*)g_l2t)[tid];
  __syncthreads();
  const u64* lwu=(const u64*)lw;
  int v=blockIdx.x*256+tid;
  int z=v/(H2*W2); int r=v%(H2*W2); int y=r/W2; int xx=r%W2;
  int v3=((z>>1)*H3+(y>>1))*W3+(xx>>1);
  u64 S[16], C[16];
#pragma unroll
  for(int j=0;j<16;j++){ S[j]=0ULL; C[j]=MZ2; }
  for(int ci=0;ci<32;ci++){
    u64 in2=bcast2(g_f2[ci*NV2+v]);
#pragma unroll
    for(int j=0;j<16;j++) kacc2(S[j],C[j],in2,lwu[ci*16+j]);
  }
  float mx=-1e30f;
#pragma unroll
  for(int j=0;j<16;j++){
    float v0,v1; unpack2(kfin2(S[j],C[j]),v0,v1);
    float p0=__fadd_rn(__fadd_rn(v0,__ldg(&b[2*j])),   g_p3[(2*j)*NV3+v3]);
    float p1=__fadd_rn(__fadd_rn(v1,__ldg(&b[2*j+1])), g_p3[(2*j+1)*NV3+v3]);
    g_p2[(2*j)*NV2+v]=p0; g_p2[(2*j+1)*NV2+v]=p1;
    mx=fmaxf(mx,fmaxf(p0,p1));
  }
  g_s2[v]=mx;
}

__global__ void p1_k(const float* __restrict__ b){
  __shared__ float lw[512];
  int tid=threadIdx.x;
  if(tid<128) ((float4*)lw)[tid]=((const float4*)g_l1t)[tid];
  __syncthreads();
  const u64* lwu=(const u64*)lw;
  int v=blockIdx.x*256+tid;
  int z=v/(H1*W1); int r=v%(H1*W1); int y=r/W1; int xx=r%W1;
  int v2=((z>>1)*H2+(y>>1))*W2+(xx>>1);
  u64 S[16], C[16];
#pragma unroll
  for(int j=0;j<16;j++){ S[j]=0ULL; C[j]=MZ2; }
  for(int ci=0;ci<16;ci++){
    u64 in2=bcast2(g_f1[ci*NV1+v]);
#pragma unroll
    for(int j=0;j<16;j++) kacc2(S[j],C[j],in2,lwu[ci*16+j]);
  }
  float mx=-1e30f;
#pragma unroll
  for(int j=0;j<16;j++){
    float v0,v1; unpack2(kfin2(S[j],C[j]),v0,v1);
    float p0=__fadd_rn(__fadd_rn(v0,__ldg(&b[2*j])),   g_p2[(2*j)*NV2+v2]);
    float p1=__fadd_rn(__fadd_rn(v1,__ldg(&b[2*j+1])), g_p2[(2*j+1)*NV2+v2]);
    g_p1[(2*j)*NV1+v]=p0; g_p1[(2*j+1)*NV1+v]=p1;
    mx=fmaxf(mx,fmaxf(p0,p1));
  }
  g_s1[v]=mx;
}

// ------------------------------------------------------------------
// exact top-K=512 per level, all levels fused via grid.y
// ------------------------------------------------------------------
__device__ __forceinline__ unsigned okey(float f){
  unsigned u=__float_as_uint(f);
  return (u & 0x80000000u) ? ~u : (u | 0x80000000u);
}
__device__ __forceinline__ float fromkey(unsigned k){
  unsigned u = (k & 0x80000000u) ? (k ^ 0x80000000u) : ~k;
  return __uint_as_float(u);
}
__device__ __forceinline__ const float* level_score(int l){
  return (l==0)? g_s1 : (l==1)? g_s2 : g_s3;
}
__device__ __forceinline__ int level_n(int l){
  return (l==0)? NV1 : (l==1)? NV2 : NV3;
}

__global__ void tk_clear(){
  int t=blockIdx.x*256+threadIdx.x;
  if(t<3*65536) ((unsigned*)g_hist16)[t]=0;
  if(t<3*256) ((unsigned*)g_hist8)[t]=0;
  if(t<3*8) ((int*)g_ctrl)[t]=0;
}
__global__ void tk_hist16(){
  int l=blockIdx.y;
  int t=blockIdx.x*256+threadIdx.x; if(t>=level_n(l))return;
  atomicAdd(&g_hist16[l][okey(level_score(l)[t])>>16],1u);
}
__global__ void tk_find16(){
  int l=blockIdx.x;
  __shared__ unsigned part[256];
  int t=threadIdx.x;
  unsigned sm=0;
  for(int i=0;i<256;i++) sm+=g_hist16[l][t*256+i];
  part[t]=sm;
  __syncthreads();
  if(t==0){
    unsigned cum=0;
    for(int c=255;c>=0;c--){
      if(cum+part[c]>=K_TOP){
        for(int bb=c*256+255;;bb--){
          unsigned h=g_hist16[l][bb];
          if(cum+h>=K_TOP){ g_ctrl[l][0]=bb; g_ctrl[l][1]=(int)cum; break; }
          cum+=h;
        }
        break;
      }
      cum+=part[c];
    }
  }
}
__global__ void tk_hist8(){
  int l=blockIdx.y;
  int t=blockIdx.x*256+threadIdx.x; if(t>=level_n(l))return;
  unsigned k=okey(level_score(l)[t]);
  if((int)(k>>16)==g_ctrl[l][0]) atomicAdd(&g_hist8[l][(k>>8)&255],1u);
}
__global__ void tk_find8(){
  int l=threadIdx.x; if(l>=3)return;
  unsigned cum=(unsigned)g_ctrl[l][1];
  int b16=g_ctrl[l][0];
  for(int bb=255;bb>=0;bb--){
    unsigned h=g_hist8[l][bb];
    if(cum+h>=K_TOP){ g_ctrl[l][2]=(b16<<8)|bb; break; }
    cum+=h;
  }
}
__global__ void tk_gather(){
  int l=blockIdx.y;
  int t=blockIdx.x*256+threadIdx.x; if(t>=level_n(l))return;
  unsigned k=okey(level_score(l)[t]);
  if((int)(k>>8) >= g_ctrl[l][2]){
    int pos=atomicAdd(&g_ctrl[l][3],1);
    if(pos<CAP){ g_candKey[l][pos]=k; g_candIdx[l][pos]=t; }
  }
}
__global__ void tk_sort(){
  int level=blockIdx.x;
  __shared__ unsigned long long a[CAP];
  int t=threadIdx.x;
  int M=min(g_ctrl[level][3],CAP);
  for(int i=t;i<CAP;i+=1024)
    a[i] = (i<M)? ((((unsigned long long)g_candKey[level][i])<<32) | (unsigned)(~g_candIdx[level][i])) : 0ULL;
  __syncthreads();
  for(int kk=2;kk<=CAP;kk<<=1){
    for(int j=kk>>1;j>0;j>>=1){
      for(int i=t;i<CAP;i+=1024){
        int ixj=i^j;
        if(ixj>i){
          bool asc=((i&kk)!=0);          // descending overall
          unsigned long long A=a[i],B=a[ixj];
          if(asc? (A>B):(A<B)){ a[i]=B; a[ixj]=A; }
        }
      }
      __syncthreads();
    }
  }
  if(t<K_TOP){
    unsigned long long c=a[t];
    g_topval[level*K_TOP+t]=fromkey((unsigned)(c>>32));
    g_topidx[level*K_TOP+t]=~((unsigned)c);
  }
}

// ------------------------------------------------------------------
// per-candidate: cube mean/std (fp64) -> MLP (fp64 accum) -> output
// ------------------------------------------------------------------
__global__ void mlp_k(const float* __restrict__ w1,const float* __restrict__ b1,
                      const float* __restrict__ w2,const float* __restrict__ b2,
                      float* __restrict__ out){
  int l=blockIdx.y; int slot=blockIdx.x; int t=threadIdx.x;
  __shared__ float feat[64];
  __shared__ float h[128];
  int D,H,W; const float* p;
  if(l==0){D=D1;H=H1;W=W1;p=g_p1;}
  else if(l==1){D=D2;H=H2;W=W2;p=g_p2;}
  else {D=D3;H=H3;W=W3;p=g_p3;}
  unsigned idx=g_topidx[l*K_TOP+slot];
  float val=g_topval[l*K_TOP+slot];
  int plane=D*H*W;
  int z=(int)idx/(H*W); int r=(int)idx%(H*W); int y=r/W; int xx=r%W;
  int zs=min(max(z-2,0),D-4);
  int ys=min(max(y-2,0),H-4);
  int xs=min(max(xx-2,0),W-4);
  if(t<32){
    float cv[64];
    const float* base = p + t*plane + (zs*H+ys)*W + xs;
#pragma unroll
    for(int dz=0;dz<4;dz++)
#pragma unroll
      for(int dy=0;dy<4;dy++)
#pragma unroll
        for(int dx=0;dx<4;dx++)
          cv[(dz*4+dy)*4+dx]=base[(dz*H+dy)*W+dx];
    double s=0.0;
#pragma unroll
    for(int i=0;i<64;i++) s+=(double)cv[i];
    double m=s*(1.0/64.0);
    double ss=0.0;
#pragma unroll
    for(int i=0;i<64;i++){ double d=(double)cv[i]-m; ss+=d*d; }
    double var=ss*(1.0/64.0);
    feat[t]=(float)m;
    feat[32+t]=(float)sqrt(var+1e-6);
  }
  __syncthreads();
  {
    double acc=0.0;
    for(int i=0;i<64;i++) acc += (double)feat[i]*(double)__ldg(&w1[i*128+t]);
    h[t]=fmaxf((float)(acc+(double)__ldg(&b1[t])),0.f);
  }
  __syncthreads();
  if(t<2){
    double acc=0.0;
    for(int j=0;j<128;j++) acc+=(double)h[j]*(double)__ldg(&w2[j*2+t]);
    float valid=(val>0.5f)?1.f:0.f;
    out[(l*K_TOP+slot)*2+t]=(float)(acc+(double)__ldg(&b2[t]))*valid;
  }
}

// ------------------------------------------------------------------
extern "C" void kernel_launch(void* const* d_in, const int* in_sizes, int n_in,
                              void* d_out, int out_size){
  const float* x  =(const float*)d_in[0];
  const float* c1w=(const float*)d_in[1];  const float* c1b=(const float*)d_in[2];
  const float* c2w=(const float*)d_in[3];  const float* c2b=(const float*)d_in[4];
  const float* c3w=(const float*)d_in[5];  const float* c3b=(const float*)d_in[6];
  const float* l1w=(const float*)d_in[7];  const float* l1b=(const float*)d_in[8];
  const float* l2w=(const float*)d_in[9];  const float* l2b=(const float*)d_in[10];
  const float* l3w=(const float*)d_in[11]; const float* l3b=(const float*)d_in[12];
  const float* w1 =(const float*)d_in[13]; const float* b1 =(const float*)d_in[14];
  const float* w2 =(const float*)d_in[15]; const float* b2 =(const float*)d_in[16];
  float* out=(float*)d_out;

  prep_k<<<216,256>>>(c1w,c2w,c3w,l1w,l2w,l3w);
  conv1_k<<<NV1/256,256>>>(x,c1b);
  conv2_k<<<dim3(NV2/256,4),256>>>(c2b);
  conv3_k<<<432,256>>>(c3b);
  p3_k<<<NV3/256,256>>>(l3b);
  p2_k<<<NV2/256,256>>>(l2b);
  p1_k<<<NV1/256,256>>>(l1b);

  int nb=(NV1+255)/256;
  tk_clear<<<768,256>>>();
  tk_hist16<<<dim3(nb,3),256>>>();
  tk_find16<<<3,256>>>();
  tk_hist8<<<dim3(nb,3),256>>>();
  tk_find8<<<1,32>>>();
  tk_gather<<<dim3(nb,3),256>>>();
  tk_sort<<<3,1024>>>();

  mlp_k<<<dim3(K_TOP,3),128>>>(w1,b1,w2,b2,out);
}